// round 15
// baseline (speedup 1.0000x reference)
#include <cuda_runtime.h>
#include <cuda_fp16.h>
#include <cstdint>

// Problem constants
#define CC 64
#define TT 128
#define FF 128
#define HH 128
#define LL 121          // F - K + 1
#define NN 512          // B*T
#define DH 256          // 2*H
#define MROWS 61952     // L*N
#define COLS4H 1024     // 2*4H

// ---------------------------------------------------------------------------
// Scratch (static device allocations - allowed)
// ---------------------------------------------------------------------------
__device__ float g_xn[4194304];      // (B,C,T,F) normed input (fp32)
__device__ __half g_U[63438848];     // (L*N, 1024) GEMM out / P buffer (fp16)
__device__ __half g_A0[31719424];    // (L*N, 512) unfold (fp16)
__device__ __half g_h[15859712];     // (L*N, 256) scan output (fp16)
__device__ __half g_Bt[1441792];     // transposed weights [n*K+k] (fp16)

// ---------------------------------------------------------------------------
// PTX helpers (base sm_103-compatible: cp.async / ldmatrix / mma.sync fp16)
// ---------------------------------------------------------------------------
__device__ __forceinline__ uint32_t smem_u32(const void* p) {
    return (uint32_t)__cvta_generic_to_shared(p);
}
__device__ __forceinline__ void cpa16(uint32_t s, const void* g) {
    asm volatile("cp.async.cg.shared.global [%0], [%1], 16;" :: "r"(s), "l"(g));
}
__device__ __forceinline__ void cp_commit() {
    asm volatile("cp.async.commit_group;" ::: "memory");
}
__device__ __forceinline__ void cp_wait1() {
    asm volatile("cp.async.wait_group 1;" ::: "memory");
}
__device__ __forceinline__ void ldm4(uint32_t* r, uint32_t a) {
    asm volatile("ldmatrix.sync.aligned.m8n8.x4.shared.b16 {%0,%1,%2,%3}, [%4];"
        : "=r"(r[0]), "=r"(r[1]), "=r"(r[2]), "=r"(r[3]) : "r"(a));
}
__device__ __forceinline__ void mma16816(float* d, const uint32_t* a, const uint32_t* b) {
    asm volatile(
        "mma.sync.aligned.m16n8k16.row.col.f32.f16.f16.f32 "
        "{%0,%1,%2,%3}, {%4,%5,%6,%7}, {%8,%9}, {%0,%1,%2,%3};"
        : "+f"(d[0]), "+f"(d[1]), "+f"(d[2]), "+f"(d[3])
        : "r"(a[0]), "r"(a[1]), "r"(a[2]), "r"(a[3]), "r"(b[0]), "r"(b[1]));
}
// fp16 tile, 64 halves/row = 8 16B-units, unit swizzled by row&7
__device__ __forceinline__ uint32_t soff64(int row, int u) {
    return (uint32_t)(((row << 3) + (u ^ (row & 7))) << 4);
}

// ---------------------------------------------------------------------------
// 1) Channel norm over C
// ---------------------------------------------------------------------------
__global__ __launch_bounds__(256) void norm_kernel(
    const float* __restrict__ x, const float* __restrict__ gamma,
    const float* __restrict__ beta)
{
    int idx = blockIdx.x * 256 + threadIdx.x;   // B*T*F = 65536
    int f = idx & 127;
    int t = (idx >> 7) & 127;
    int b = idx >> 14;
    long base = ((long)b * CC * TT * FF) + (long)t * FF + f;
    const float* xp = x + base;
    float v[CC];
    float s = 0.f;
#pragma unroll
    for (int c = 0; c < CC; ++c) { v[c] = xp[(long)c * TT * FF]; s += v[c]; }
    float mu = s * (1.f / 64.f);
    float vs = 0.f;
#pragma unroll
    for (int c = 0; c < CC; ++c) { float d = v[c] - mu; vs += d * d; }
    float inv = rsqrtf(vs * (1.f / 64.f) + 1e-8f);
    float* op = g_xn + base;
#pragma unroll
    for (int c = 0; c < CC; ++c)
        op[(long)c * TT * FF] = gamma[c] * (v[c] - mu) * inv + beta[c];
}

// ---------------------------------------------------------------------------
// 2) Unfold -> A0 fp16. One thread = one (row, c): 8 elems = 16B store.
// ---------------------------------------------------------------------------
__global__ __launch_bounds__(256) void unfold_kernel()
{
    long q = (long)blockIdx.x * 256 + threadIdx.x;   // 3964928 = 31719424/8
    if (q >= 3964928L) return;
    int c = (int)(q & 63);
    long row = q >> 6;          // l*512 + n
    int n = (int)(row & 511);
    int l = (int)(row >> 9);
    int b = n >> 7;
    int t = n & 127;
    const float* src = g_xn + (((long)(b * CC + c) * TT + t) << 7) + l;
    __half2 h[4];
#pragma unroll
    for (int j = 0; j < 4; ++j)
        h[j] = __floats2half2_rn(src[2 * j], src[2 * j + 1]);
    *(uint4*)(g_A0 + row * 512 + c * 8) = *(uint4*)h;
}

// ---------------------------------------------------------------------------
// 3) Weight transpose + fp16, gate-interleaved column permutation.
// ---------------------------------------------------------------------------
__global__ __launch_bounds__(256) void wsplit_kernel(
    const float* __restrict__ W0, const float* __restrict__ W1,
    const float* __restrict__ W2, const float* __restrict__ W3,
    const float* __restrict__ Wc)
{
    long idx = (long)blockIdx.x * 256 + threadIdx.x;
    if (idx >= 1441792L) return;
    const float* W; long off; int Ktot, Nfull; bool perm = true;
    if (idx < 524288L)        { W = W0; off = 0L;        Ktot = 512; Nfull = 1024; }
    else if (idx < 786432L)   { W = W1; off = 524288L;   Ktot = 256; Nfull = 1024; }
    else if (idx < 1048576L)  { W = W2; off = 786432L;   Ktot = 256; Nfull = 1024; }
    else if (idx < 1310720L)  { W = W3; off = 1048576L;  Ktot = 256; Nfull = 1024; }
    else                      { W = Wc; off = 1310720L;  Ktot = 256; Nfull = 512; perm = false; }
    long li = idx - off;
    int n = (int)(li / Ktot);
    int k = (int)(li % Ktot);
    int src = n;
    if (perm) {
        int d = n >> 9, r = n & 511;
        int h = r >> 2, g = r & 3;
        src = d * 512 + g * 128 + h;
    }
    g_Bt[idx] = __float2half_rn(W[(long)k * Nfull + src]);
}

// ---------------------------------------------------------------------------
// 4) fp16 mma.sync GEMM: C(M x N) = A(M x Ktot) * Bt^T, fp16 out to g_U.
//    CTA tile 128x128, BK=64, 8 warps (warp tile 32x64), 3-stage cp.async.
//    Stage: A 16K | B 16K = 32K; 3 stages = 96K -> 2 CTAs/SM.
// ---------------------------------------------------------------------------
#define STB 32768
#define SMEM_DYN (3 * STB)

__global__ __launch_bounds__(256, 2) void mma_gemm(
    int aId, long wOff, int Ktot, int Nstride)
{
    extern __shared__ __align__(16) char sm[];
    const __half* __restrict__ Ap = aId ? g_h : g_A0;
    const __half* __restrict__ Bp = g_Bt + wOff;

    const int tid = threadIdx.x;
    const int wid = tid >> 5;
    const int lane = tid & 31;
    const long bm = (long)blockIdx.y * 128;
    const long bn = (long)blockIdx.x * 128;
    const int wm = (wid & 3) * 32;
    const int wn = (wid >> 2) * 64;
    const int KT = Ktot >> 6;

    // global->smem: 16B per cpa16 (8 halves); 128 rows x 8 units per operand
    const int lu = tid & 7;                      // unit 0..7
    const int lr = tid >> 3;                     // row 0..31
    const long rK = 32L * Ktot;
    const long gaoff = (bm + lr) * (long)Ktot + lu * 8;
    const long gboff = (bn + lr) * (long)Ktot + lu * 8;

    // ldmatrix lane mapping (validated rounds 3/10)
    const int grp = lane >> 3;
    const int l8 = lane & 7;
    const int arow0 = wm + (grp & 1) * 8 + l8;   // + mf*16
    const int auadd = grp >> 1;                  // + ks*2
    const int brow0 = wn + (grp >> 1) * 8 + l8;  // + np*16
    const int buadd = grp & 1;                   // + ks*2

    float acc[2][8][4];
#pragma unroll
    for (int i = 0; i < 2; ++i)
#pragma unroll
        for (int j = 0; j < 8; ++j)
#pragma unroll
            for (int q = 0; q < 4; ++q) acc[i][j][q] = 0.f;

    auto stage_of = [&](int kt) -> char* { return sm + (kt % 3) * STB; };

    auto issue = [&](int kt) {
        uint32_t sa = smem_u32(stage_of(kt));
        long k0 = (long)kt * 64;
        const __half* a = Ap + gaoff + k0;
        const __half* b = Bp + gboff + k0;
#pragma unroll
        for (int i = 0; i < 4; ++i)
            cpa16(sa + soff64(lr + i * 32, lu), a + i * rK);
#pragma unroll
        for (int i = 0; i < 4; ++i)
            cpa16(sa + 16384 + soff64(lr + i * 32, lu), b + i * rK);
    };

    auto compute = [&](int kt) {
        uint32_t sA = smem_u32(stage_of(kt));
        uint32_t sB = sA + 16384;
#pragma unroll
        for (int ks = 0; ks < 4; ++ks) {
            uint32_t a[2][4], b[4][4];
#pragma unroll
            for (int mf = 0; mf < 2; ++mf)
                ldm4(a[mf], sA + soff64(arow0 + mf * 16, ks * 2 + auadd));
#pragma unroll
            for (int np = 0; np < 4; ++np)
                ldm4(b[np], sB + soff64(brow0 + np * 16, ks * 2 + buadd));
#pragma unroll
            for (int mf = 0; mf < 2; ++mf)
#pragma unroll
                for (int nf = 0; nf < 8; ++nf)
                    mma16816(acc[mf][nf], a[mf], &b[nf >> 1][(nf & 1) * 2]);
        }
    };

    issue(0); cp_commit();
    issue(1); cp_commit();
    cp_wait1();
    __syncthreads();

    for (int kt = 0; kt < KT; ++kt) {
        if (kt + 2 < KT) issue(kt + 2);
        cp_commit();
        compute(kt);
        cp_wait1();
        __syncthreads();
    }

    // Epilogue (fp16): c0,c1 at (row, col), c2,c3 at (row+8, col)
    const int er = lane >> 2;
    const int ec = (lane & 3) * 2;
#pragma unroll
    for (int mf = 0; mf < 2; ++mf)
#pragma unroll
        for (int nf = 0; nf < 8; ++nf) {
            __half* p = g_U + (bm + wm + mf * 16 + er) * (long)Nstride
                            + bn + wn + nf * 8 + ec;
            *(__half2*)p = __floats2half2_rn(acc[mf][nf][0], acc[mf][nf][1]);
            *(__half2*)(p + 8L * Nstride) =
                __floats2half2_rn(acc[mf][nf][2], acc[mf][nf][3]);
        }
}

// ---------------------------------------------------------------------------
// 5) SRU scan: gate-interleaved fp16 U (uint2 per dir per step), prefetch 4
// ---------------------------------------------------------------------------
#define PFD 4
__global__ __launch_bounds__(256) void scan_kernel(
    const float* __restrict__ bf, const float* __restrict__ br)
{
    int t = blockIdx.x * 256 + threadIdx.x;   // 131072 lanes
    int hidx = t & 127;
    int n = (t >> 7) & 511;
    int dir = t >> 16;

    float bfv = bf[dir * HH + hidx];
    float brv = br[dir * HH + hidx];

    const long ustepE = (long)NN * COLS4H;      // halves per l-step
    const long ostepF = (long)NN * DH;
    const long ostride = dir ? -ostepF : ostepF;

    const uint2* u = (const uint2*)(g_U + (long)n * COLS4H + dir * 512 + hidx * 4
                                    + (dir ? (LL - 1) * ustepE : 0));
    const long ustride4 = (dir ? -ustepE : ustepE) >> 2;   // uint2 stride
    long oi = (long)n * DH + dir * HH + hidx + (dir ? (LL - 1) * ostepF : 0);

    uint2 v[PFD];
#pragma unroll
    for (int i = 0; i < PFD; ++i)
        v[i] = (i < LL) ? u[i * ustride4] : make_uint2(0, 0);

    float c = 0.f;
    for (int l = 0; l < LL; ++l) {
        uint2 vn = make_uint2(0, 0);
        if (l + PFD < LL) vn = u[PFD * ustride4];
        float2 zf = __half22float2(*(__half2*)&v[0].x);   // (z, f)
        float2 rp = __half22float2(*(__half2*)&v[0].y);   // (r, hp)
        float fs = 1.f / (1.f + __expf(-(zf.y + bfv)));
        float rs = 1.f / (1.f + __expf(-(rp.x + brv)));
        c = fs * c + (1.f - fs) * zf.x;
        g_h[oi] = __float2half_rn(rs * c + (1.f - rs) * rp.y);
#pragma unroll
        for (int i = 0; i < PFD - 1; ++i) v[i] = v[i + 1];
        v[PFD - 1] = vn;
        u += ustride4; oi += ostride;
    }
}

// ---------------------------------------------------------------------------
// 6) ConvTranspose gather + bias + residual. One block per n; coalesced
//    32-bit staging of the full (LL x 512) fp16 P slice into smem.
//    A row is 512 halves = 256 words. Pitch 514 halves = 257 words
//    (gcd(257,32)=1 -> conflict-free compute); 4B accesses always aligned.
// ---------------------------------------------------------------------------
#define SPITCH 514
#define GATHER_SMEM (LL * SPITCH * 2)

__global__ __launch_bounds__(256) void gather_kernel(
    const float* __restrict__ convb, float* __restrict__ out)
{
    extern __shared__ __half sP[];
    int n = blockIdx.x;
    int tid = threadIdx.x;

    // Stage P[l, :] rows (512 halves = 256 uint words each), coalesced.
    for (int idx = tid; idx < LL * 256; idx += 256) {
        int l = idx >> 8, j = idx & 255;
        *(uint32_t*)(sP + l * SPITCH + j * 2) =
            *(const uint32_t*)(g_U + ((long)(l * NN + n)) * 512 + j * 2);
    }
    __syncthreads();

    int f = tid & 127;
    int cg = tid >> 7;           // 0 or 1
    int b = n >> 7, t = n & 127;

    for (int ci = 0; ci < 32; ++ci) {
        int c = cg * 32 + ci;
        float acc = convb[c];
#pragma unroll
        for (int k = 0; k < 8; ++k) {
            int l = f - k;
            if (l >= 0 && l < LL)
                acc += __half2float(sP[l * SPITCH + c * 8 + k]);
        }
        long oi = (((long)(b * CC + c) * TT + t) << 7) + f;
        out[oi] = acc + g_xn[oi];
    }
}

// ---------------------------------------------------------------------------
// Launch
// ---------------------------------------------------------------------------
extern "C" void kernel_launch(void* const* d_in, const int* in_sizes, int n_in,
                              void* d_out, int out_size)
{
    const float* x     = (const float*)d_in[0];
    const float* gamma = (const float*)d_in[1];
    const float* beta  = (const float*)d_in[2];
    const float* W0  = (const float*)d_in[3];
    const float* bf0 = (const float*)d_in[4];
    const float* br0 = (const float*)d_in[5];
    const float* W1  = (const float*)d_in[6];
    const float* bf1 = (const float*)d_in[7];
    const float* br1 = (const float*)d_in[8];
    const float* W2  = (const float*)d_in[9];
    const float* bf2 = (const float*)d_in[10];
    const float* br2 = (const float*)d_in[11];
    const float* W3  = (const float*)d_in[12];
    const float* bf3 = (const float*)d_in[13];
    const float* br3 = (const float*)d_in[14];
    const float* convW = (const float*)d_in[15];
    const float* convb = (const float*)d_in[16];
    float* out = (float*)d_out;

    cudaFuncSetAttribute(mma_gemm, cudaFuncAttributeMaxDynamicSharedMemorySize,
                         SMEM_DYN);
    cudaFuncSetAttribute(gather_kernel,
                         cudaFuncAttributeMaxDynamicSharedMemorySize,
                         GATHER_SMEM);

    wsplit_kernel<<<5632, 256>>>(W0, W1, W2, W3, convW);
    norm_kernel<<<256, 256>>>(x, gamma, beta);
    unfold_kernel<<<15488, 256>>>();

    dim3 gU(8, 484);   // N=1024: 8 N-tiles of 128
    dim3 gP(4, 484);   // N=512:  4 N-tiles of 128

    // Layer 0 (K=512)
    mma_gemm<<<gU, 256, SMEM_DYN>>>(0, 0L, 512, 1024);
    scan_kernel<<<512, 256>>>(bf0, br0);
    // Layers 1-3 (K=256)
    mma_gemm<<<gU, 256, SMEM_DYN>>>(1, 524288L, 256, 1024);
    scan_kernel<<<512, 256>>>(bf1, br1);
    mma_gemm<<<gU, 256, SMEM_DYN>>>(1, 786432L, 256, 1024);
    scan_kernel<<<512, 256>>>(bf2, br2);
    mma_gemm<<<gU, 256, SMEM_DYN>>>(1, 1048576L, 256, 1024);
    scan_kernel<<<512, 256>>>(bf3, br3);

    // ConvTranspose as GEMM: P = h4 @ convW^T  (M x 512, K=256)
    mma_gemm<<<gP, 256, SMEM_DYN>>>(1, 1310720L, 256, 512);

    gather_kernel<<<NN, 256, GATHER_SMEM>>>(convb, out);
}

// round 16
// speedup vs baseline: 1.0992x; 1.0992x over previous
#include <cuda_runtime.h>
#include <cuda_fp16.h>
#include <cstdint>

// Problem constants
#define CC 64
#define TT 128
#define FF 128
#define HH 128
#define LL 121          // F - K + 1
#define NN 512          // B*T
#define DH 256          // 2*H
#define MROWS 61952     // L*N
#define COLS4H 1024     // 2*4H

// ---------------------------------------------------------------------------
// Scratch (static device allocations - allowed)
// ---------------------------------------------------------------------------
__device__ float g_xn[4194304];      // (B,C,T,F) normed input (fp32)
__device__ __half g_U[63438848];     // (L*N, 1024) GEMM out / P buffer (fp16)
__device__ __half g_A0[31719424];    // (L*N, 512) unfold (fp16)
__device__ __half g_h[15859712];     // (L*N, 256) scan output (fp16)
__device__ __half g_Bt[1441792];     // transposed weights [n*K+k] (fp16)

// ---------------------------------------------------------------------------
// PTX helpers (base sm_103-compatible: cp.async / ldmatrix / mma.sync fp16)
// ---------------------------------------------------------------------------
__device__ __forceinline__ uint32_t smem_u32(const void* p) {
    return (uint32_t)__cvta_generic_to_shared(p);
}
__device__ __forceinline__ void cpa16(uint32_t s, const void* g) {
    asm volatile("cp.async.cg.shared.global [%0], [%1], 16;" :: "r"(s), "l"(g));
}
__device__ __forceinline__ void cp_commit() {
    asm volatile("cp.async.commit_group;" ::: "memory");
}
__device__ __forceinline__ void cp_wait1() {
    asm volatile("cp.async.wait_group 1;" ::: "memory");
}
__device__ __forceinline__ void ldm4(uint32_t* r, uint32_t a) {
    asm volatile("ldmatrix.sync.aligned.m8n8.x4.shared.b16 {%0,%1,%2,%3}, [%4];"
        : "=r"(r[0]), "=r"(r[1]), "=r"(r[2]), "=r"(r[3]) : "r"(a));
}
__device__ __forceinline__ void mma16816(float* d, const uint32_t* a, const uint32_t* b) {
    asm volatile(
        "mma.sync.aligned.m16n8k16.row.col.f32.f16.f16.f32 "
        "{%0,%1,%2,%3}, {%4,%5,%6,%7}, {%8,%9}, {%0,%1,%2,%3};"
        : "+f"(d[0]), "+f"(d[1]), "+f"(d[2]), "+f"(d[3])
        : "r"(a[0]), "r"(a[1]), "r"(a[2]), "r"(a[3]), "r"(b[0]), "r"(b[1]));
}
// fp16 tile, 64 halves/row = 8 16B-units, unit swizzled by row&7
__device__ __forceinline__ uint32_t soff64(int row, int u) {
    return (uint32_t)(((row << 3) + (u ^ (row & 7))) << 4);
}

// ---------------------------------------------------------------------------
// 1) Channel norm over C
// ---------------------------------------------------------------------------
__global__ __launch_bounds__(256) void norm_kernel(
    const float* __restrict__ x, const float* __restrict__ gamma,
    const float* __restrict__ beta)
{
    int idx = blockIdx.x * 256 + threadIdx.x;   // B*T*F = 65536
    int f = idx & 127;
    int t = (idx >> 7) & 127;
    int b = idx >> 14;
    long base = ((long)b * CC * TT * FF) + (long)t * FF + f;
    const float* xp = x + base;
    float v[CC];
    float s = 0.f;
#pragma unroll
    for (int c = 0; c < CC; ++c) { v[c] = xp[(long)c * TT * FF]; s += v[c]; }
    float mu = s * (1.f / 64.f);
    float vs = 0.f;
#pragma unroll
    for (int c = 0; c < CC; ++c) { float d = v[c] - mu; vs += d * d; }
    float inv = rsqrtf(vs * (1.f / 64.f) + 1e-8f);
    float* op = g_xn + base;
#pragma unroll
    for (int c = 0; c < CC; ++c)
        op[(long)c * TT * FF] = gamma[c] * (v[c] - mu) * inv + beta[c];
}

// ---------------------------------------------------------------------------
// 2) Unfold -> A0 fp16. One thread = one (row, c): 8 elems = 16B store.
// ---------------------------------------------------------------------------
__global__ __launch_bounds__(256) void unfold_kernel()
{
    long q = (long)blockIdx.x * 256 + threadIdx.x;   // 3964928 = 31719424/8
    if (q >= 3964928L) return;
    int c = (int)(q & 63);
    long row = q >> 6;          // l*512 + n
    int n = (int)(row & 511);
    int l = (int)(row >> 9);
    int b = n >> 7;
    int t = n & 127;
    const float* src = g_xn + (((long)(b * CC + c) * TT + t) << 7) + l;
    __half2 h[4];
#pragma unroll
    for (int j = 0; j < 4; ++j)
        h[j] = __floats2half2_rn(src[2 * j], src[2 * j + 1]);
    *(uint4*)(g_A0 + row * 512 + c * 8) = *(uint4*)h;
}

// ---------------------------------------------------------------------------
// 3) Weight transpose + fp16, gate-interleaved column permutation.
// ---------------------------------------------------------------------------
__global__ __launch_bounds__(256) void wsplit_kernel(
    const float* __restrict__ W0, const float* __restrict__ W1,
    const float* __restrict__ W2, const float* __restrict__ W3,
    const float* __restrict__ Wc)
{
    long idx = (long)blockIdx.x * 256 + threadIdx.x;
    if (idx >= 1441792L) return;
    const float* W; long off; int Ktot, Nfull; bool perm = true;
    if (idx < 524288L)        { W = W0; off = 0L;        Ktot = 512; Nfull = 1024; }
    else if (idx < 786432L)   { W = W1; off = 524288L;   Ktot = 256; Nfull = 1024; }
    else if (idx < 1048576L)  { W = W2; off = 786432L;   Ktot = 256; Nfull = 1024; }
    else if (idx < 1310720L)  { W = W3; off = 1048576L;  Ktot = 256; Nfull = 1024; }
    else                      { W = Wc; off = 1310720L;  Ktot = 256; Nfull = 512; perm = false; }
    long li = idx - off;
    int n = (int)(li / Ktot);
    int k = (int)(li % Ktot);
    int src = n;
    if (perm) {
        int d = n >> 9, r = n & 511;
        int h = r >> 2, g = r & 3;
        src = d * 512 + g * 128 + h;
    }
    g_Bt[idx] = __float2half_rn(W[(long)k * Nfull + src]);
}

// ---------------------------------------------------------------------------
// 4) fp16 mma.sync GEMM: C(M x N) = A(M x Ktot) * Bt^T, fp16 out to g_U.
//    CTA tile 128x128, BK=64, 8 warps (warp tile 32x64), 3-stage cp.async.
//    Stage: A 16K | B 16K = 32K; 3 stages = 96K -> 2 CTAs/SM.
// ---------------------------------------------------------------------------
#define STB 32768
#define SMEM_DYN (3 * STB)

__global__ __launch_bounds__(256, 2) void mma_gemm(
    int aId, long wOff, int Ktot, int Nstride)
{
    extern __shared__ __align__(16) char sm[];
    const __half* __restrict__ Ap = aId ? g_h : g_A0;
    const __half* __restrict__ Bp = g_Bt + wOff;

    const int tid = threadIdx.x;
    const int wid = tid >> 5;
    const int lane = tid & 31;
    const long bm = (long)blockIdx.y * 128;
    const long bn = (long)blockIdx.x * 128;
    const int wm = (wid & 3) * 32;
    const int wn = (wid >> 2) * 64;
    const int KT = Ktot >> 6;

    // global->smem: 16B per cpa16 (8 halves); 128 rows x 8 units per operand
    const int lu = tid & 7;                      // unit 0..7
    const int lr = tid >> 3;                     // row 0..31
    const long rK = 32L * Ktot;
    const long gaoff = (bm + lr) * (long)Ktot + lu * 8;
    const long gboff = (bn + lr) * (long)Ktot + lu * 8;

    // ldmatrix lane mapping (validated rounds 3/10)
    const int grp = lane >> 3;
    const int l8 = lane & 7;
    const int arow0 = wm + (grp & 1) * 8 + l8;   // + mf*16
    const int auadd = grp >> 1;                  // + ks*2
    const int brow0 = wn + (grp >> 1) * 8 + l8;  // + np*16
    const int buadd = grp & 1;                   // + ks*2

    float acc[2][8][4];
#pragma unroll
    for (int i = 0; i < 2; ++i)
#pragma unroll
        for (int j = 0; j < 8; ++j)
#pragma unroll
            for (int q = 0; q < 4; ++q) acc[i][j][q] = 0.f;

    auto stage_of = [&](int kt) -> char* { return sm + (kt % 3) * STB; };

    auto issue = [&](int kt) {
        uint32_t sa = smem_u32(stage_of(kt));
        long k0 = (long)kt * 64;
        const __half* a = Ap + gaoff + k0;
        const __half* b = Bp + gboff + k0;
#pragma unroll
        for (int i = 0; i < 4; ++i)
            cpa16(sa + soff64(lr + i * 32, lu), a + i * rK);
#pragma unroll
        for (int i = 0; i < 4; ++i)
            cpa16(sa + 16384 + soff64(lr + i * 32, lu), b + i * rK);
    };

    auto compute = [&](int kt) {
        uint32_t sA = smem_u32(stage_of(kt));
        uint32_t sB = sA + 16384;
#pragma unroll
        for (int ks = 0; ks < 4; ++ks) {
            uint32_t a[2][4], b[4][4];
#pragma unroll
            for (int mf = 0; mf < 2; ++mf)
                ldm4(a[mf], sA + soff64(arow0 + mf * 16, ks * 2 + auadd));
#pragma unroll
            for (int np = 0; np < 4; ++np)
                ldm4(b[np], sB + soff64(brow0 + np * 16, ks * 2 + buadd));
#pragma unroll
            for (int mf = 0; mf < 2; ++mf)
#pragma unroll
                for (int nf = 0; nf < 8; ++nf)
                    mma16816(acc[mf][nf], a[mf], &b[nf >> 1][(nf & 1) * 2]);
        }
    };

    issue(0); cp_commit();
    issue(1); cp_commit();
    cp_wait1();
    __syncthreads();

    for (int kt = 0; kt < KT; ++kt) {
        if (kt + 2 < KT) issue(kt + 2);
        cp_commit();
        compute(kt);
        cp_wait1();
        __syncthreads();
    }

    // Epilogue (fp16): c0,c1 at (row, col), c2,c3 at (row+8, col)
    const int er = lane >> 2;
    const int ec = (lane & 3) * 2;
#pragma unroll
    for (int mf = 0; mf < 2; ++mf)
#pragma unroll
        for (int nf = 0; nf < 8; ++nf) {
            __half* p = g_U + (bm + wm + mf * 16 + er) * (long)Nstride
                            + bn + wn + nf * 8 + ec;
            *(__half2*)p = __floats2half2_rn(acc[mf][nf][0], acc[mf][nf][1]);
            *(__half2*)(p + 8L * Nstride) =
                __floats2half2_rn(acc[mf][nf][2], acc[mf][nf][3]);
        }
}

// ---------------------------------------------------------------------------
// 5) SRU scan: gate-interleaved fp16 U (uint2 per dir per step), prefetch 4
// ---------------------------------------------------------------------------
#define PFD 4
__global__ __launch_bounds__(256) void scan_kernel(
    const float* __restrict__ bf, const float* __restrict__ br)
{
    int t = blockIdx.x * 256 + threadIdx.x;   // 131072 lanes
    int hidx = t & 127;
    int n = (t >> 7) & 511;
    int dir = t >> 16;

    float bfv = bf[dir * HH + hidx];
    float brv = br[dir * HH + hidx];

    const long ustepE = (long)NN * COLS4H;      // halves per l-step
    const long ostepF = (long)NN * DH;
    const long ostride = dir ? -ostepF : ostepF;

    const uint2* u = (const uint2*)(g_U + (long)n * COLS4H + dir * 512 + hidx * 4
                                    + (dir ? (LL - 1) * ustepE : 0));
    const long ustride4 = (dir ? -ustepE : ustepE) >> 2;   // uint2 stride
    long oi = (long)n * DH + dir * HH + hidx + (dir ? (LL - 1) * ostepF : 0);

    uint2 v[PFD];
#pragma unroll
    for (int i = 0; i < PFD; ++i)
        v[i] = (i < LL) ? u[i * ustride4] : make_uint2(0, 0);

    float c = 0.f;
    for (int l = 0; l < LL; ++l) {
        uint2 vn = make_uint2(0, 0);
        if (l + PFD < LL) vn = u[PFD * ustride4];
        float2 zf = __half22float2(*(__half2*)&v[0].x);   // (z, f)
        float2 rp = __half22float2(*(__half2*)&v[0].y);   // (r, hp)
        float fs = 1.f / (1.f + __expf(-(zf.y + bfv)));
        float rs = 1.f / (1.f + __expf(-(rp.x + brv)));
        c = fs * c + (1.f - fs) * zf.x;
        g_h[oi] = __float2half_rn(rs * c + (1.f - rs) * rp.y);
#pragma unroll
        for (int i = 0; i < PFD - 1; ++i) v[i] = v[i + 1];
        v[PFD - 1] = vn;
        u += ustride4; oi += ostride;
    }
}

// ---------------------------------------------------------------------------
// 6) ConvTranspose gather + bias + residual. Block = (n, group of 8 c's).
//    Stage 121 x 64 halves (~16 KB smem, pitch 66 -> stride 33 words,
//    gcd(33,32)=1 conflict-free). ~14 blocks/SM. g_U read fully coalesced.
// ---------------------------------------------------------------------------
#define GP 66
#define GATHER_SMEM (LL * GP * 2)

__global__ __launch_bounds__(128) void gather_kernel(
    const float* __restrict__ convb, float* __restrict__ out)
{
    extern __shared__ __half sP[];
    int n = blockIdx.x;
    int cg = blockIdx.y;         // 0..7, channels cg*8 .. cg*8+7
    int tid = threadIdx.x;       // 128 threads

    // Stage: per l, 64 halves = 32 words (128 B contiguous), coalesced.
    for (int idx = tid; idx < LL * 32; idx += 128) {
        int l = idx >> 5, j = idx & 31;
        *(uint32_t*)(sP + l * GP + j * 2) =
            *(const uint32_t*)(g_U + ((long)(l * NN + n)) * 512 + cg * 64 + j * 2);
    }
    __syncthreads();

    int f = tid;                 // 0..127
    int b = n >> 7, t = n & 127;

#pragma unroll
    for (int ci = 0; ci < 8; ++ci) {
        int c = cg * 8 + ci;
        float acc = convb[c];
#pragma unroll
        for (int k = 0; k < 8; ++k) {
            int l = f - k;
            if (l >= 0 && l < LL)
                acc += __half2float(sP[l * GP + ci * 8 + k]);
        }
        long oi = (((long)(b * CC + c) * TT + t) << 7) + f;
        out[oi] = acc + g_xn[oi];
    }
}

// ---------------------------------------------------------------------------
// Launch
// ---------------------------------------------------------------------------
extern "C" void kernel_launch(void* const* d_in, const int* in_sizes, int n_in,
                              void* d_out, int out_size)
{
    const float* x     = (const float*)d_in[0];
    const float* gamma = (const float*)d_in[1];
    const float* beta  = (const float*)d_in[2];
    const float* W0  = (const float*)d_in[3];
    const float* bf0 = (const float*)d_in[4];
    const float* br0 = (const float*)d_in[5];
    const float* W1  = (const float*)d_in[6];
    const float* bf1 = (const float*)d_in[7];
    const float* br1 = (const float*)d_in[8];
    const float* W2  = (const float*)d_in[9];
    const float* bf2 = (const float*)d_in[10];
    const float* br2 = (const float*)d_in[11];
    const float* W3  = (const float*)d_in[12];
    const float* bf3 = (const float*)d_in[13];
    const float* br3 = (const float*)d_in[14];
    const float* convW = (const float*)d_in[15];
    const float* convb = (const float*)d_in[16];
    float* out = (float*)d_out;

    cudaFuncSetAttribute(mma_gemm, cudaFuncAttributeMaxDynamicSharedMemorySize,
                         SMEM_DYN);
    cudaFuncSetAttribute(gather_kernel,
                         cudaFuncAttributeMaxDynamicSharedMemorySize,
                         GATHER_SMEM);

    wsplit_kernel<<<5632, 256>>>(W0, W1, W2, W3, convW);
    norm_kernel<<<256, 256>>>(x, gamma, beta);
    unfold_kernel<<<15488, 256>>>();

    dim3 gU(8, 484);   // N=1024: 8 N-tiles of 128
    dim3 gP(4, 484);   // N=512:  4 N-tiles of 128

    // Layer 0 (K=512)
    mma_gemm<<<gU, 256, SMEM_DYN>>>(0, 0L, 512, 1024);
    scan_kernel<<<512, 256>>>(bf0, br0);
    // Layers 1-3 (K=256)
    mma_gemm<<<gU, 256, SMEM_DYN>>>(1, 524288L, 256, 1024);
    scan_kernel<<<512, 256>>>(bf1, br1);
    mma_gemm<<<gU, 256, SMEM_DYN>>>(1, 786432L, 256, 1024);
    scan_kernel<<<512, 256>>>(bf2, br2);
    mma_gemm<<<gU, 256, SMEM_DYN>>>(1, 1048576L, 256, 1024);
    scan_kernel<<<512, 256>>>(bf3, br3);

    // ConvTranspose as GEMM: P = h4 @ convW^T  (M x 512, K=256)
    mma_gemm<<<gP, 256, SMEM_DYN>>>(1, 1310720L, 256, 512);

    dim3 gg(NN, 8);
    gather_kernel<<<gg, 128, GATHER_SMEM>>>(convb, out);
}

// round 17
// speedup vs baseline: 1.1373x; 1.0347x over previous
#include <cuda_runtime.h>
#include <cuda_fp16.h>
#include <cstdint>

// Problem constants
#define CC 64
#define TT 128
#define FF 128
#define HH 128
#define LL 121          // F - K + 1
#define NN 512          // B*T
#define DH 256          // 2*H
#define MROWS 61952     // L*N
#define COLS4H 1024     // 2*4H

// ---------------------------------------------------------------------------
// Scratch (static device allocations - allowed)
// ---------------------------------------------------------------------------
__device__ float g_xn[4194304];      // (B,C,T,F) normed input (fp32)
__device__ __half g_U[63438848];     // (L*N, 1024) GEMM out / P buffer (fp16)
__device__ __half g_A0[31719424];    // (L*N, 512) unfold (fp16)
__device__ __half g_h[15859712];     // (L*N, 256) scan output (fp16)
__device__ __half g_Bt[1441792];     // transposed weights [n*K+k] (fp16)

// ---------------------------------------------------------------------------
// PTX helpers (base sm_103-compatible: cp.async / ldmatrix / mma.sync fp16)
// ---------------------------------------------------------------------------
__device__ __forceinline__ uint32_t smem_u32(const void* p) {
    return (uint32_t)__cvta_generic_to_shared(p);
}
__device__ __forceinline__ void cpa16(uint32_t s, const void* g) {
    asm volatile("cp.async.cg.shared.global [%0], [%1], 16;" :: "r"(s), "l"(g));
}
__device__ __forceinline__ void cp_commit() {
    asm volatile("cp.async.commit_group;" ::: "memory");
}
__device__ __forceinline__ void cp_wait1() {
    asm volatile("cp.async.wait_group 1;" ::: "memory");
}
__device__ __forceinline__ void ldm4(uint32_t* r, uint32_t a) {
    asm volatile("ldmatrix.sync.aligned.m8n8.x4.shared.b16 {%0,%1,%2,%3}, [%4];"
        : "=r"(r[0]), "=r"(r[1]), "=r"(r[2]), "=r"(r[3]) : "r"(a));
}
__device__ __forceinline__ void mma16816(float* d, const uint32_t* a, const uint32_t* b) {
    asm volatile(
        "mma.sync.aligned.m16n8k16.row.col.f32.f16.f16.f32 "
        "{%0,%1,%2,%3}, {%4,%5,%6,%7}, {%8,%9}, {%0,%1,%2,%3};"
        : "+f"(d[0]), "+f"(d[1]), "+f"(d[2]), "+f"(d[3])
        : "r"(a[0]), "r"(a[1]), "r"(a[2]), "r"(a[3]), "r"(b[0]), "r"(b[1]));
}
// fp16 tile, 64 halves/row = 8 16B-units, unit swizzled by row&7
__device__ __forceinline__ uint32_t soff64(int row, int u) {
    return (uint32_t)(((row << 3) + (u ^ (row & 7))) << 4);
}

// ---------------------------------------------------------------------------
// 1) Channel norm over C
// ---------------------------------------------------------------------------
__global__ __launch_bounds__(256) void norm_kernel(
    const float* __restrict__ x, const float* __restrict__ gamma,
    const float* __restrict__ beta)
{
    int idx = blockIdx.x * 256 + threadIdx.x;   // B*T*F = 65536
    int f = idx & 127;
    int t = (idx >> 7) & 127;
    int b = idx >> 14;
    long base = ((long)b * CC * TT * FF) + (long)t * FF + f;
    const float* xp = x + base;
    float v[CC];
    float s = 0.f;
#pragma unroll
    for (int c = 0; c < CC; ++c) { v[c] = xp[(long)c * TT * FF]; s += v[c]; }
    float mu = s * (1.f / 64.f);
    float vs = 0.f;
#pragma unroll
    for (int c = 0; c < CC; ++c) { float d = v[c] - mu; vs += d * d; }
    float inv = rsqrtf(vs * (1.f / 64.f) + 1e-8f);
    float* op = g_xn + base;
#pragma unroll
    for (int c = 0; c < CC; ++c)
        op[(long)c * TT * FF] = gamma[c] * (v[c] - mu) * inv + beta[c];
}

// ---------------------------------------------------------------------------
// 2) Unfold -> A0 fp16. One thread = one (row, c): 8 elems = 16B store.
// ---------------------------------------------------------------------------
__global__ __launch_bounds__(256) void unfold_kernel()
{
    long q = (long)blockIdx.x * 256 + threadIdx.x;   // 3964928 = 31719424/8
    if (q >= 3964928L) return;
    int c = (int)(q & 63);
    long row = q >> 6;          // l*512 + n
    int n = (int)(row & 511);
    int l = (int)(row >> 9);
    int b = n >> 7;
    int t = n & 127;
    const float* src = g_xn + (((long)(b * CC + c) * TT + t) << 7) + l;
    __half2 h[4];
#pragma unroll
    for (int j = 0; j < 4; ++j)
        h[j] = __floats2half2_rn(src[2 * j], src[2 * j + 1]);
    *(uint4*)(g_A0 + row * 512 + c * 8) = *(uint4*)h;
}

// ---------------------------------------------------------------------------
// 3) Weight transpose + fp16, gate-interleaved column permutation.
// ---------------------------------------------------------------------------
__global__ __launch_bounds__(256) void wsplit_kernel(
    const float* __restrict__ W0, const float* __restrict__ W1,
    const float* __restrict__ W2, const float* __restrict__ W3,
    const float* __restrict__ Wc)
{
    long idx = (long)blockIdx.x * 256 + threadIdx.x;
    if (idx >= 1441792L) return;
    const float* W; long off; int Ktot, Nfull; bool perm = true;
    if (idx < 524288L)        { W = W0; off = 0L;        Ktot = 512; Nfull = 1024; }
    else if (idx < 786432L)   { W = W1; off = 524288L;   Ktot = 256; Nfull = 1024; }
    else if (idx < 1048576L)  { W = W2; off = 786432L;   Ktot = 256; Nfull = 1024; }
    else if (idx < 1310720L)  { W = W3; off = 1048576L;  Ktot = 256; Nfull = 1024; }
    else                      { W = Wc; off = 1310720L;  Ktot = 256; Nfull = 512; perm = false; }
    long li = idx - off;
    int n = (int)(li / Ktot);
    int k = (int)(li % Ktot);
    int src = n;
    if (perm) {
        int d = n >> 9, r = n & 511;
        int h = r >> 2, g = r & 3;
        src = d * 512 + g * 128 + h;
    }
    g_Bt[idx] = __float2half_rn(W[(long)k * Nfull + src]);
}

// ---------------------------------------------------------------------------
// 4) fp16 mma.sync GEMM: C(M x N) = A(M x Ktot) * Bt^T, fp16 out to g_U.
//    CTA tile 128x128, BK=64, 8 warps (warp tile 32x64), 3-stage cp.async.
//    Stage: A 16K | B 16K = 32K; 3 stages = 96K -> 2 CTAs/SM.
// ---------------------------------------------------------------------------
#define STB 32768
#define SMEM_DYN (3 * STB)

__global__ __launch_bounds__(256, 2) void mma_gemm(
    int aId, long wOff, int Ktot, int Nstride)
{
    extern __shared__ __align__(16) char sm[];
    const __half* __restrict__ Ap = aId ? g_h : g_A0;
    const __half* __restrict__ Bp = g_Bt + wOff;

    const int tid = threadIdx.x;
    const int wid = tid >> 5;
    const int lane = tid & 31;
    const long bm = (long)blockIdx.y * 128;
    const long bn = (long)blockIdx.x * 128;
    const int wm = (wid & 3) * 32;
    const int wn = (wid >> 2) * 64;
    const int KT = Ktot >> 6;

    // global->smem: 16B per cpa16 (8 halves); 128 rows x 8 units per operand
    const int lu = tid & 7;                      // unit 0..7
    const int lr = tid >> 3;                     // row 0..31
    const long rK = 32L * Ktot;
    const long gaoff = (bm + lr) * (long)Ktot + lu * 8;
    const long gboff = (bn + lr) * (long)Ktot + lu * 8;

    // ldmatrix lane mapping (validated rounds 3/10)
    const int grp = lane >> 3;
    const int l8 = lane & 7;
    const int arow0 = wm + (grp & 1) * 8 + l8;   // + mf*16
    const int auadd = grp >> 1;                  // + ks*2
    const int brow0 = wn + (grp >> 1) * 8 + l8;  // + np*16
    const int buadd = grp & 1;                   // + ks*2

    float acc[2][8][4];
#pragma unroll
    for (int i = 0; i < 2; ++i)
#pragma unroll
        for (int j = 0; j < 8; ++j)
#pragma unroll
            for (int q = 0; q < 4; ++q) acc[i][j][q] = 0.f;

    auto stage_of = [&](int kt) -> char* { return sm + (kt % 3) * STB; };

    auto issue = [&](int kt) {
        uint32_t sa = smem_u32(stage_of(kt));
        long k0 = (long)kt * 64;
        const __half* a = Ap + gaoff + k0;
        const __half* b = Bp + gboff + k0;
#pragma unroll
        for (int i = 0; i < 4; ++i)
            cpa16(sa + soff64(lr + i * 32, lu), a + i * rK);
#pragma unroll
        for (int i = 0; i < 4; ++i)
            cpa16(sa + 16384 + soff64(lr + i * 32, lu), b + i * rK);
    };

    auto compute = [&](int kt) {
        uint32_t sA = smem_u32(stage_of(kt));
        uint32_t sB = sA + 16384;
#pragma unroll
        for (int ks = 0; ks < 4; ++ks) {
            uint32_t a[2][4], b[4][4];
#pragma unroll
            for (int mf = 0; mf < 2; ++mf)
                ldm4(a[mf], sA + soff64(arow0 + mf * 16, ks * 2 + auadd));
#pragma unroll
            for (int np = 0; np < 4; ++np)
                ldm4(b[np], sB + soff64(brow0 + np * 16, ks * 2 + buadd));
#pragma unroll
            for (int mf = 0; mf < 2; ++mf)
#pragma unroll
                for (int nf = 0; nf < 8; ++nf)
                    mma16816(acc[mf][nf], a[mf], &b[nf >> 1][(nf & 1) * 2]);
        }
    };

    issue(0); cp_commit();
    issue(1); cp_commit();
    cp_wait1();
    __syncthreads();

    for (int kt = 0; kt < KT; ++kt) {
        if (kt + 2 < KT) issue(kt + 2);
        cp_commit();
        compute(kt);
        cp_wait1();
        __syncthreads();
    }

    // Epilogue (fp16): c0,c1 at (row, col), c2,c3 at (row+8, col)
    const int er = lane >> 2;
    const int ec = (lane & 3) * 2;
#pragma unroll
    for (int mf = 0; mf < 2; ++mf)
#pragma unroll
        for (int nf = 0; nf < 8; ++nf) {
            __half* p = g_U + (bm + wm + mf * 16 + er) * (long)Nstride
                            + bn + wn + nf * 8 + ec;
            *(__half2*)p = __floats2half2_rn(acc[mf][nf][0], acc[mf][nf][1]);
            *(__half2*)(p + 8L * Nstride) =
                __floats2half2_rn(acc[mf][nf][2], acc[mf][nf][3]);
        }
}

// ---------------------------------------------------------------------------
// 5) SRU scan: gate-interleaved fp16 U (uint2 per dir per step), prefetch 4.
//    Sigmoid via __expf + __fdividef (MUFU.RCP) instead of div.rn.
// ---------------------------------------------------------------------------
#define PFD 4
__global__ __launch_bounds__(256) void scan_kernel(
    const float* __restrict__ bf, const float* __restrict__ br)
{
    int t = blockIdx.x * 256 + threadIdx.x;   // 131072 lanes
    int hidx = t & 127;
    int n = (t >> 7) & 511;
    int dir = t >> 16;

    float bfv = bf[dir * HH + hidx];
    float brv = br[dir * HH + hidx];

    const long ustepE = (long)NN * COLS4H;      // halves per l-step
    const long ostepF = (long)NN * DH;
    const long ostride = dir ? -ostepF : ostepF;

    const uint2* u = (const uint2*)(g_U + (long)n * COLS4H + dir * 512 + hidx * 4
                                    + (dir ? (LL - 1) * ustepE : 0));
    const long ustride4 = (dir ? -ustepE : ustepE) >> 2;   // uint2 stride
    long oi = (long)n * DH + dir * HH + hidx + (dir ? (LL - 1) * ostepF : 0);

    uint2 v[PFD];
#pragma unroll
    for (int i = 0; i < PFD; ++i)
        v[i] = (i < LL) ? u[i * ustride4] : make_uint2(0, 0);

    float c = 0.f;
    for (int l = 0; l < LL; ++l) {
        uint2 vn = make_uint2(0, 0);
        if (l + PFD < LL) vn = u[PFD * ustride4];
        float2 zf = __half22float2(*(__half2*)&v[0].x);   // (z, f)
        float2 rp = __half22float2(*(__half2*)&v[0].y);   // (r, hp)
        float fs = __fdividef(1.f, 1.f + __expf(-(zf.y + bfv)));
        float rs = __fdividef(1.f, 1.f + __expf(-(rp.x + brv)));
        c = fs * c + (1.f - fs) * zf.x;
        g_h[oi] = __float2half_rn(rs * c + (1.f - rs) * rp.y);
#pragma unroll
        for (int i = 0; i < PFD - 1; ++i) v[i] = v[i + 1];
        v[PFD - 1] = vn;
        u += ustride4; oi += ostride;
    }
}

// ---------------------------------------------------------------------------
// 6) ConvTranspose gather + bias + residual. Block = (n, group of 8 c's).
//    Stage 121 x 64 halves (~16 KB smem, pitch 66 -> stride 33 words,
//    gcd(33,32)=1 conflict-free). ~14 blocks/SM. g_U read fully coalesced.
// ---------------------------------------------------------------------------
#define GP 66
#define GATHER_SMEM (LL * GP * 2)

__global__ __launch_bounds__(128) void gather_kernel(
    const float* __restrict__ convb, float* __restrict__ out)
{
    extern __shared__ __half sP[];
    int n = blockIdx.x;
    int cg = blockIdx.y;         // 0..7, channels cg*8 .. cg*8+7
    int tid = threadIdx.x;       // 128 threads

    // Stage: per l, 64 halves = 32 words (128 B contiguous), coalesced.
    for (int idx = tid; idx < LL * 32; idx += 128) {
        int l = idx >> 5, j = idx & 31;
        *(uint32_t*)(sP + l * GP + j * 2) =
            *(const uint32_t*)(g_U + ((long)(l * NN + n)) * 512 + cg * 64 + j * 2);
    }
    __syncthreads();

    int f = tid;                 // 0..127
    int b = n >> 7, t = n & 127;

#pragma unroll
    for (int ci = 0; ci < 8; ++ci) {
        int c = cg * 8 + ci;
        float acc = convb[c];
#pragma unroll
        for (int k = 0; k < 8; ++k) {
            int l = f - k;
            if (l >= 0 && l < LL)
                acc += __half2float(sP[l * GP + ci * 8 + k]);
        }
        long oi = (((long)(b * CC + c) * TT + t) << 7) + f;
        out[oi] = acc + g_xn[oi];
    }
}

// ---------------------------------------------------------------------------
// Launch
// ---------------------------------------------------------------------------
extern "C" void kernel_launch(void* const* d_in, const int* in_sizes, int n_in,
                              void* d_out, int out_size)
{
    const float* x     = (const float*)d_in[0];
    const float* gamma = (const float*)d_in[1];
    const float* beta  = (const float*)d_in[2];
    const float* W0  = (const float*)d_in[3];
    const float* bf0 = (const float*)d_in[4];
    const float* br0 = (const float*)d_in[5];
    const float* W1  = (const float*)d_in[6];
    const float* bf1 = (const float*)d_in[7];
    const float* br1 = (const float*)d_in[8];
    const float* W2  = (const float*)d_in[9];
    const float* bf2 = (const float*)d_in[10];
    const float* br2 = (const float*)d_in[11];
    const float* W3  = (const float*)d_in[12];
    const float* bf3 = (const float*)d_in[13];
    const float* br3 = (const float*)d_in[14];
    const float* convW = (const float*)d_in[15];
    const float* convb = (const float*)d_in[16];
    float* out = (float*)d_out;

    cudaFuncSetAttribute(mma_gemm, cudaFuncAttributeMaxDynamicSharedMemorySize,
                         SMEM_DYN);
    cudaFuncSetAttribute(gather_kernel,
                         cudaFuncAttributeMaxDynamicSharedMemorySize,
                         GATHER_SMEM);

    wsplit_kernel<<<5632, 256>>>(W0, W1, W2, W3, convW);
    norm_kernel<<<256, 256>>>(x, gamma, beta);
    unfold_kernel<<<15488, 256>>>();

    dim3 gU(8, 484);   // N=1024: 8 N-tiles of 128
    dim3 gP(4, 484);   // N=512:  4 N-tiles of 128

    // Layer 0 (K=512)
    mma_gemm<<<gU, 256, SMEM_DYN>>>(0, 0L, 512, 1024);
    scan_kernel<<<512, 256>>>(bf0, br0);
    // Layers 1-3 (K=256)
    mma_gemm<<<gU, 256, SMEM_DYN>>>(1, 524288L, 256, 1024);
    scan_kernel<<<512, 256>>>(bf1, br1);
    mma_gemm<<<gU, 256, SMEM_DYN>>>(1, 786432L, 256, 1024);
    scan_kernel<<<512, 256>>>(bf2, br2);
    mma_gemm<<<gU, 256, SMEM_DYN>>>(1, 1048576L, 256, 1024);
    scan_kernel<<<512, 256>>>(bf3, br3);

    // ConvTranspose as GEMM: P = h4 @ convW^T  (M x 512, K=256)
    mma_gemm<<<gP, 256, SMEM_DYN>>>(1, 1310720L, 256, 512);

    dim3 gg(NN, 8);
    gather_kernel<<<gg, 128, GATHER_SMEM>>>(convb, out);
}